// round 12
// baseline (speedup 1.0000x reference)
#include <cuda_runtime.h>
#include <cuda_bf16.h>
#include <cstdint>

#define TOKENS   8192
#define DIMV     1024
#define HEADS    16
#define HD       64
#define NSEQ     1024
#define NBATCH   8
#define ATT_SCALE 0.125f
#define N_QKV    3072
#define NBH      (NBATCH * HEADS)

// ---------------- scratch (__device__ globals; no allocation) ---------------
__device__ __align__(16) __nv_bfloat16 g_xh[(size_t)TOKENS * DIMV];
__device__ __align__(16) __nv_bfloat16 g_xl[(size_t)TOKENS * DIMV];
__device__ __align__(16) __nv_bfloat16 g_atth[(size_t)TOKENS * DIMV];
__device__ __align__(16) __nv_bfloat16 g_attl[(size_t)TOKENS * DIMV];
__device__ __align__(16) __nv_bfloat16 g_wqkv_h[(size_t)N_QKV * DIMV];
__device__ __align__(16) __nv_bfloat16 g_wqkv_l[(size_t)N_QKV * DIMV];
__device__ __align__(16) __nv_bfloat16 g_wproj_h[(size_t)DIMV * DIMV];
__device__ __align__(16) __nv_bfloat16 g_wproj_l[(size_t)DIMV * DIMV];
// head-major split QKV: [bh][n][64]
__device__ __align__(16) __nv_bfloat16 g_qh[(size_t)NBH * NSEQ * HD];
__device__ __align__(16) __nv_bfloat16 g_ql[(size_t)NBH * NSEQ * HD];
__device__ __align__(16) __nv_bfloat16 g_kh[(size_t)NBH * NSEQ * HD];
__device__ __align__(16) __nv_bfloat16 g_kl[(size_t)NBH * NSEQ * HD];
__device__ __align__(16) __nv_bfloat16 g_vh[(size_t)NBH * NSEQ * HD];
__device__ __align__(16) __nv_bfloat16 g_vl[(size_t)NBH * NSEQ * HD];

// ---------------- helpers ----------------
__device__ __forceinline__ uint32_t smem_u32(const void* p) {
    uint32_t a;
    asm("{ .reg .u64 t; cvta.to.shared.u64 t, %1; cvt.u32.u64 %0, t; }" : "=r"(a) : "l"(p));
    return a;
}
__device__ __forceinline__ void ldm4(uint32_t* r, uint32_t addr) {
    asm volatile("ldmatrix.sync.aligned.m8n8.x4.shared.b16 {%0,%1,%2,%3}, [%4];"
                 : "=r"(r[0]), "=r"(r[1]), "=r"(r[2]), "=r"(r[3]) : "r"(addr));
}
__device__ __forceinline__ void ldm4t(uint32_t* r, uint32_t addr) {
    asm volatile("ldmatrix.sync.aligned.m8n8.x4.trans.shared.b16 {%0,%1,%2,%3}, [%4];"
                 : "=r"(r[0]), "=r"(r[1]), "=r"(r[2]), "=r"(r[3]) : "r"(addr));
}
__device__ __forceinline__ void mma_bf16(float* d, const uint32_t* a,
                                         uint32_t b0, uint32_t b1) {
    asm volatile(
        "mma.sync.aligned.m16n8k16.row.col.f32.bf16.bf16.f32 "
        "{%0,%1,%2,%3}, {%4,%5,%6,%7}, {%8,%9}, {%0,%1,%2,%3};"
        : "+f"(d[0]), "+f"(d[1]), "+f"(d[2]), "+f"(d[3])
        : "r"(a[0]), "r"(a[1]), "r"(a[2]), "r"(a[3]), "r"(b0), "r"(b1));
}
__device__ __forceinline__ void bf16_split(float v, __nv_bfloat16& h, __nv_bfloat16& l) {
    h = __float2bfloat16(v);
    l = __float2bfloat16(v - __bfloat162float(h));
}
__device__ __forceinline__ void split_pack(float a, float b, uint32_t& h, uint32_t& l) {
    __nv_bfloat16 ha = __float2bfloat16(a), hb = __float2bfloat16(b);
    float ra = a - __bfloat162float(ha), rb = b - __bfloat162float(hb);
    __nv_bfloat162 H(ha, hb);
    __nv_bfloat162 L(__float2bfloat16(ra), __float2bfloat16(rb));
    h = *reinterpret_cast<uint32_t*>(&H);
    l = *reinterpret_cast<uint32_t*>(&L);
}
#define CP_ASYNC16(s, g) asm volatile("cp.async.cg.shared.global [%0], [%1], 16;" :: "r"(s), "l"(g))
#define CP_COMMIT()      asm volatile("cp.async.commit_group;" ::: "memory")
#define CP_WAIT1()       asm volatile("cp.async.wait_group 1;" ::: "memory")
#define CP_WAIT0()       asm volatile("cp.async.wait_group 0;" ::: "memory")
// XOR-16B swizzled offset within a [rows][8x16B] array
#define SWZ_OFF(row, c)  ((((row) * 8 + ((c) ^ ((row) & 7)))) * 16)

// ---------------------------------------------------------------------------
// Weight transpose + bf16 hi/lo split: W[K,N] -> Th/Tl[N,K]
// ---------------------------------------------------------------------------
__global__ __launch_bounds__(256) void transpose_split_kernel(
    const float* __restrict__ W, __nv_bfloat16* __restrict__ Th,
    __nv_bfloat16* __restrict__ Tl, int K, int N) {
    __shared__ float t[32][33];
    const int tx = threadIdx.x, ty = threadIdx.y;
    const int k0 = blockIdx.x * 32, n0 = blockIdx.y * 32;
    #pragma unroll
    for (int i = 0; i < 4; i++)
        t[ty + i * 8][tx] = W[(size_t)(k0 + ty + i * 8) * N + (n0 + tx)];
    __syncthreads();
    #pragma unroll
    for (int i = 0; i < 4; i++) {
        const float v = t[tx][ty + i * 8];
        __nv_bfloat16 h, l;
        bf16_split(v, h, l);
        const size_t o = (size_t)(n0 + ty + i * 8) * K + (k0 + tx);
        Th[o] = h;
        Tl[o] = l;
    }
}

// ---------------------------------------------------------------------------
// split x fp32 -> xh/xl bf16 (same layout)
// ---------------------------------------------------------------------------
__global__ __launch_bounds__(256) void split_x_kernel(const float* __restrict__ x) {
    const size_t o = (size_t)blockIdx.x * DIMV + threadIdx.x * 4;
    float4 v = *reinterpret_cast<const float4*>(x + o);
    uint32_t h0, l0, h1, l1;
    split_pack(v.x, v.y, h0, l0);
    split_pack(v.z, v.w, h1, l1);
    *reinterpret_cast<uint32_t*>(g_xh + o)     = h0;
    *reinterpret_cast<uint32_t*>(g_xh + o + 2) = h1;
    *reinterpret_cast<uint32_t*>(g_xl + o)     = l0;
    *reinterpret_cast<uint32_t*>(g_xl + o + 2) = l1;
}

// ---------------------------------------------------------------------------
// Pipelined bf16x3 GEMM, pre-split A: C = A @ Bt^T.
// MODE 1: fp32 C + bias.  MODE 2: scatter to split head-major QKV.
// CTA tile 128(M)x64(N), BK=64, 256 threads = 8 warps 4(m)x2(n), warp 32x32.
// Term-major MMA ordering: accumulator RAW distance 4 (was 1).
// ---------------------------------------------------------------------------
#define GA_BYTES 16384                     // 128 rows * 128 B
#define GB_BYTES 8192                      // 64 rows * 128 B
#define OFF_AL GA_BYTES
#define OFF_BH (2 * GA_BYTES)
#define OFF_BL (2 * GA_BYTES + GB_BYTES)
#define GS_STAGE (2 * GA_BYTES + 2 * GB_BYTES)   // 49152
#define GS_SMEM  (2 * GS_STAGE)                  // 98304

template<int MODE>
__global__ __launch_bounds__(256, 2) void gemm_ps_kernel(
    const __nv_bfloat16* __restrict__ Ah, const __nv_bfloat16* __restrict__ Al,
    const __nv_bfloat16* __restrict__ Bh, const __nv_bfloat16* __restrict__ Bl,
    const float* __restrict__ bias, float* __restrict__ C,
    int M, int N, int K) {
    extern __shared__ char smem[];
    const uint32_t sb = smem_u32(smem);
    const int tid  = threadIdx.x;
    const int wid  = tid >> 5;
    const int lane = tid & 31;
    const int warp_m = wid >> 1;
    const int warp_n = wid & 1;
    const int row0 = blockIdx.y * 128, col0 = blockIdx.x * 64;
    const int lr = lane & 15, ls = lane >> 4;

    auto load_tile = [&](int kc, int stage) {
        const int k0 = kc * 64;
        const uint32_t sbase = sb + stage * GS_STAGE;
        #pragma unroll
        for (int i = 0; i < 8; i++) {
            const int cid = tid + i * 256;
            const int hl = cid >> 10, rem = cid & 1023, row = rem >> 3, c = rem & 7;
            const __nv_bfloat16* src = hl ? Al : Ah;
            const void* g = src + (size_t)(row0 + row) * K + k0 + c * 8;
            CP_ASYNC16(sbase + hl * OFF_AL + SWZ_OFF(row, c), g);
        }
        #pragma unroll
        for (int i = 0; i < 4; i++) {
            const int x = tid + i * 256;
            const int hl = x >> 9, rem = x & 511, row = rem >> 3, c = rem & 7;
            const __nv_bfloat16* src = hl ? Bl : Bh;
            const void* g = src + (size_t)(col0 + row) * K + k0 + c * 8;
            CP_ASYNC16(sbase + OFF_BH + hl * GB_BYTES + SWZ_OFF(row, c), g);
        }
        CP_COMMIT();
    };

    float acc[2][4][4];
    #pragma unroll
    for (int i = 0; i < 2; i++)
        #pragma unroll
        for (int j = 0; j < 4; j++)
            #pragma unroll
            for (int r = 0; r < 4; r++) acc[i][j][r] = 0.f;

    const int nchunks = K / 64;           // 16
    load_tile(0, 0);

    for (int kc = 0; kc < nchunks; kc++) {
        const int stg = kc & 1;
        if (kc + 1 < nchunks) { load_tile(kc + 1, stg ^ 1); CP_WAIT1(); }
        else                  { CP_WAIT0(); }
        __syncthreads();

        const uint32_t base = sb + stg * GS_STAGE;
        #pragma unroll
        for (int k16 = 0; k16 < 64; k16 += 16) {
            const int cbase = (k16 >> 3) + ls;
            uint32_t b_h[2][4], b_l[2][4];
            #pragma unroll
            for (int p = 0; p < 2; p++) {
                const int r = warp_n * 32 + p * 16 + lr;
                const uint32_t off = SWZ_OFF(r, cbase);
                ldm4(b_h[p], base + OFF_BH + off);
                ldm4(b_l[p], base + OFF_BL + off);
            }
            #pragma unroll
            for (int mi = 0; mi < 2; mi++) {
                uint32_t a_h[4], a_l[4];
                const int r = warp_m * 32 + mi * 16 + lr;
                const uint32_t off = SWZ_OFF(r, cbase);
                ldm4(a_h, base + off);
                ldm4(a_l, base + OFF_AL + off);
                // Term-major: per accumulator the order is still hh -> hl -> lh,
                // but consecutive MMAs hit different accumulators (RAW dist 4).
                #pragma unroll
                for (int nj = 0; nj < 4; nj++) {
                    const int p = nj >> 1, s = nj & 1;
                    mma_bf16(acc[mi][nj], a_h, b_h[p][s], b_h[p][2 + s]);
                }
                #pragma unroll
                for (int nj = 0; nj < 4; nj++) {
                    const int p = nj >> 1, s = nj & 1;
                    mma_bf16(acc[mi][nj], a_h, b_l[p][s], b_l[p][2 + s]);
                }
                #pragma unroll
                for (int nj = 0; nj < 4; nj++) {
                    const int p = nj >> 1, s = nj & 1;
                    mma_bf16(acc[mi][nj], a_l, b_h[p][s], b_h[p][2 + s]);
                }
            }
        }
        __syncthreads();
    }

    // ---- epilogue ----
    const int er = lane >> 2, ec = (lane & 3) * 2;
    if (MODE == 2) {
        auto scatter = [&](int r, int c, float x, float y) {
            const int qi = c >> 10, dcol = c & 1023;
            const int head = dcol >> 6, dd = dcol & 63;
            const int b = r >> 10, n = r & 1023;
            const size_t off = (((size_t)(b * HEADS + head) * NSEQ) + n) * HD + dd;
            if (qi == 0) { x *= ATT_SCALE; y *= ATT_SCALE; }
            uint32_t h, l;
            split_pack(x, y, h, l);
            __nv_bfloat16* dh = (qi == 0) ? g_qh : (qi == 1) ? g_kh : g_vh;
            __nv_bfloat16* dl = (qi == 0) ? g_ql : (qi == 1) ? g_kl : g_vl;
            *reinterpret_cast<uint32_t*>(dh + off) = h;
            *reinterpret_cast<uint32_t*>(dl + off) = l;
        };
        #pragma unroll
        for (int mi = 0; mi < 2; mi++)
            #pragma unroll
            for (int nj = 0; nj < 4; nj++) {
                const int r = row0 + warp_m * 32 + mi * 16 + er;
                const int c = col0 + warp_n * 32 + nj * 8 + ec;
                scatter(r,     c, acc[mi][nj][0], acc[mi][nj][1]);
                scatter(r + 8, c, acc[mi][nj][2], acc[mi][nj][3]);
            }
    } else {
        #pragma unroll
        for (int mi = 0; mi < 2; mi++)
            #pragma unroll
            for (int nj = 0; nj < 4; nj++) {
                const int r = row0 + warp_m * 32 + mi * 16 + er;
                const int c = col0 + warp_n * 32 + nj * 8 + ec;
                float2 v0 = make_float2(acc[mi][nj][0], acc[mi][nj][1]);
                float2 v1 = make_float2(acc[mi][nj][2], acc[mi][nj][3]);
                if (MODE == 1) {
                    const float b0 = bias[c], b1 = bias[c + 1];
                    v0.x += b0; v0.y += b1;
                    v1.x += b0; v1.y += b1;
                }
                *reinterpret_cast<float2*>(C + (size_t)r * N + c)       = v0;
                *reinterpret_cast<float2*>(C + (size_t)(r + 8) * N + c) = v1;
            }
    }
}

// ---------------------------------------------------------------------------
// Flash attention, mma.sync bf16x3. MMA chains interleaved across accumulators.
// ---------------------------------------------------------------------------
#define ATT_SMEM 98304

__global__ __launch_bounds__(256) void attn_mma_kernel() {
    extern __shared__ char smem[];
    const uint32_t sb = smem_u32(smem);
    const int tid = threadIdx.x, wid = tid >> 5, lane = tid & 31;
    const int bh = blockIdx.x;
    const int qt0 = blockIdx.y * 128;
    const size_t hb = (size_t)bh * NSEQ * HD;

    {
        const __nv_bfloat16* qsrc[2] = {g_qh, g_ql};
        #pragma unroll
        for (int i = 0; i < 8; i++) {
            const int cid = tid + i * 256;
            const int arr = cid >> 10, rem = cid & 1023, row = rem >> 3, c = rem & 7;
            const void* g = qsrc[arr] + hb + (size_t)(qt0 + row) * HD + c * 8;
            const uint32_t s = sb + 65536 + arr * 16384 + SWZ_OFF(row, c);
            CP_ASYNC16(s, g);
        }
        CP_COMMIT();
    }
    auto load_kv = [&](int kt, int stage) {
        const __nv_bfloat16* src[4] = {g_kh, g_kl, g_vh, g_vl};
        const int key0 = kt * 64;
        #pragma unroll
        for (int i = 0; i < 8; i++) {
            const int cid = tid + i * 256;
            const int arr = cid >> 9, rem = cid & 511, key = rem >> 3, c = rem & 7;
            const void* g = src[arr] + hb + (size_t)(key0 + key) * HD + c * 8;
            const uint32_t s = sb + stage * 32768 + arr * 8192 + SWZ_OFF(key, c);
            CP_ASYNC16(s, g);
        }
        CP_COMMIT();
    };
    load_kv(0, 0);

    CP_WAIT1();
    __syncthreads();

    uint32_t qfh[4][4], qfl[4][4];
    {
        const int row = wid * 16 + (lane & 15);
        #pragma unroll
        for (int ks = 0; ks < 4; ks++) {
            const int c = ks * 2 + (lane >> 4);
            const uint32_t off = SWZ_OFF(row, c);
            ldm4(qfh[ks], sb + 65536 + off);
            ldm4(qfl[ks], sb + 65536 + 16384 + off);
        }
    }

    float o[8][4];
    #pragma unroll
    for (int i = 0; i < 8; i++)
        #pragma unroll
        for (int j = 0; j < 4; j++) o[i][j] = 0.f;
    float m0 = -1e30f, m1 = -1e30f, l0 = 0.f, l1 = 0.f;

    for (int kt = 0; kt < 16; kt++) {
        const int stg = kt & 1;
        if (kt + 1 < 16) { load_kv(kt + 1, stg ^ 1); CP_WAIT1(); }
        else             { CP_WAIT0(); }
        __syncthreads();

        float sc[8][4];
        #pragma unroll
        for (int i = 0; i < 8; i++)
            #pragma unroll
            for (int j = 0; j < 4; j++) sc[i][j] = 0.f;
        const uint32_t kbh = sb + stg * 32768, kbl = kbh + 8192;
        #pragma unroll
        for (int ks = 0; ks < 4; ks++) {
            #pragma unroll
            for (int g = 0; g < 4; g++) {
                const int key = g * 16 + (lane & 15);
                const int c   = ks * 2 + (lane >> 4);
                const uint32_t off = SWZ_OFF(key, c);
                uint32_t kh4[4], kl4[4];
                ldm4(kh4, kbh + off);
                ldm4(kl4, kbl + off);
                // term-major across s2: per-accumulator order hh->hl->lh kept,
                // consecutive MMAs alternate accumulators (RAW dist 2)
                float* d0 = sc[2 * g];
                float* d1 = sc[2 * g + 1];
                mma_bf16(d0, qfh[ks], kh4[0], kh4[2]);
                mma_bf16(d1, qfh[ks], kh4[1], kh4[3]);
                mma_bf16(d0, qfh[ks], kl4[0], kl4[2]);
                mma_bf16(d1, qfh[ks], kl4[1], kl4[3]);
                mma_bf16(d0, qfl[ks], kh4[0], kh4[2]);
                mma_bf16(d1, qfl[ks], kh4[1], kh4[3]);
            }
        }

        float mx0 = sc[0][0], mx1 = sc[0][2];
        #pragma unroll
        for (int nt = 0; nt < 8; nt++) {
            mx0 = fmaxf(mx0, fmaxf(sc[nt][0], sc[nt][1]));
            mx1 = fmaxf(mx1, fmaxf(sc[nt][2], sc[nt][3]));
        }
        mx0 = fmaxf(mx0, __shfl_xor_sync(0xffffffffu, mx0, 1));
        mx0 = fmaxf(mx0, __shfl_xor_sync(0xffffffffu, mx0, 2));
        mx1 = fmaxf(mx1, __shfl_xor_sync(0xffffffffu, mx1, 1));
        mx1 = fmaxf(mx1, __shfl_xor_sync(0xffffffffu, mx1, 2));
        const float mn0 = fmaxf(m0, mx0), mn1 = fmaxf(m1, mx1);
        const float c0 = __expf(m0 - mn0), c1 = __expf(m1 - mn1);
        float s0 = 0.f, s1 = 0.f;
        #pragma unroll
        for (int nt = 0; nt < 8; nt++) {
            float p0 = __expf(sc[nt][0] - mn0); sc[nt][0] = p0; s0 += p0;
            float p1 = __expf(sc[nt][1] - mn0); sc[nt][1] = p1; s0 += p1;
            float p2 = __expf(sc[nt][2] - mn1); sc[nt][2] = p2; s1 += p2;
            float p3 = __expf(sc[nt][3] - mn1); sc[nt][3] = p3; s1 += p3;
        }
        s0 += __shfl_xor_sync(0xffffffffu, s0, 1);
        s0 += __shfl_xor_sync(0xffffffffu, s0, 2);
        s1 += __shfl_xor_sync(0xffffffffu, s1, 1);
        s1 += __shfl_xor_sync(0xffffffffu, s1, 2);
        l0 = l0 * c0 + s0; l1 = l1 * c1 + s1;
        m0 = mn0; m1 = mn1;
        #pragma unroll
        for (int dt = 0; dt < 8; dt++) {
            o[dt][0] *= c0; o[dt][1] *= c0;
            o[dt][2] *= c1; o[dt][3] *= c1;
        }

        const uint32_t vbh = sb + stg * 32768 + 16384, vbl = vbh + 8192;
        #pragma unroll
        for (int kk = 0; kk < 4; kk++) {
            uint32_t pah[4], pal[4];
            split_pack(sc[2 * kk][0],     sc[2 * kk][1],     pah[0], pal[0]);
            split_pack(sc[2 * kk][2],     sc[2 * kk][3],     pah[1], pal[1]);
            split_pack(sc[2 * kk + 1][0], sc[2 * kk + 1][1], pah[2], pal[2]);
            split_pack(sc[2 * kk + 1][2], sc[2 * kk + 1][3], pah[3], pal[3]);
            #pragma unroll
            for (int dg = 0; dg < 4; dg++) {
                const int key = kk * 16 + (lane & 15);
                const int c   = dg * 2 + (lane >> 4);
                const uint32_t off = SWZ_OFF(key, c);
                uint32_t vh4[4], vl4[4];
                ldm4t(vh4, vbh + off);
                ldm4t(vl4, vbl + off);
                // interleave the two accumulators (RAW dist 2), per-acc order kept
                float* d0 = o[2 * dg];
                float* d1 = o[2 * dg + 1];
                mma_bf16(d0, pah, vh4[0], vh4[1]);
                mma_bf16(d1, pah, vh4[2], vh4[3]);
                mma_bf16(d0, pah, vl4[0], vl4[1]);
                mma_bf16(d1, pah, vl4[2], vl4[3]);
                mma_bf16(d0, pal, vh4[0], vh4[1]);
                mma_bf16(d1, pal, vh4[2], vh4[3]);
            }
        }
        __syncthreads();
    }

    // ---- epilogue: write split bf16 attention output (token-major [8192,1024]) ----
    const float i0 = 1.f / l0, i1 = 1.f / l1;
    const int b = bh >> 4, h = bh & 15;
    const int r0 = qt0 + wid * 16 + (lane >> 2);
    const size_t base = (size_t)(b * NSEQ + r0) * DIMV + h * HD + (lane & 3) * 2;
    #pragma unroll
    for (int dt = 0; dt < 8; dt++) {
        uint32_t h0, l0v, h1, l1v;
        split_pack(o[dt][0] * i0, o[dt][1] * i0, h0, l0v);
        split_pack(o[dt][2] * i1, o[dt][3] * i1, h1, l1v);
        *reinterpret_cast<uint32_t*>(g_atth + base + dt * 8)            = h0;
        *reinterpret_cast<uint32_t*>(g_attl + base + dt * 8)            = l0v;
        *reinterpret_cast<uint32_t*>(g_atth + base + 8 * DIMV + dt * 8) = h1;
        *reinterpret_cast<uint32_t*>(g_attl + base + 8 * DIMV + dt * 8) = l1v;
    }
}

// ---------------------------------------------------------------------------
extern "C" void kernel_launch(void* const* d_in, const int* in_sizes, int n_in,
                              void* d_out, int out_size) {
    const float* x      = (const float*)d_in[0];
    const float* w_qkv  = (const float*)d_in[1];
    const float* w_proj = (const float*)d_in[2];
    const float* b_proj = (const float*)d_in[3];
    float* out = (float*)d_out;

    __nv_bfloat16 *wq_h, *wq_l, *wp_h, *wp_l, *xh, *xl, *ath, *atl;
    cudaGetSymbolAddress((void**)&wq_h, g_wqkv_h);
    cudaGetSymbolAddress((void**)&wq_l, g_wqkv_l);
    cudaGetSymbolAddress((void**)&wp_h, g_wproj_h);
    cudaGetSymbolAddress((void**)&wp_l, g_wproj_l);
    cudaGetSymbolAddress((void**)&xh, g_xh);
    cudaGetSymbolAddress((void**)&xl, g_xl);
    cudaGetSymbolAddress((void**)&ath, g_atth);
    cudaGetSymbolAddress((void**)&atl, g_attl);

    cudaFuncSetAttribute(attn_mma_kernel,
                         cudaFuncAttributeMaxDynamicSharedMemorySize, ATT_SMEM);
    cudaFuncSetAttribute(gemm_ps_kernel<1>,
                         cudaFuncAttributeMaxDynamicSharedMemorySize, GS_SMEM);
    cudaFuncSetAttribute(gemm_ps_kernel<2>,
                         cudaFuncAttributeMaxDynamicSharedMemorySize, GS_SMEM);

    transpose_split_kernel<<<dim3(DIMV / 32, N_QKV / 32), dim3(32, 8)>>>(
        w_qkv, wq_h, wq_l, DIMV, N_QKV);
    transpose_split_kernel<<<dim3(DIMV / 32, DIMV / 32), dim3(32, 8)>>>(
        w_proj, wp_h, wp_l, DIMV, DIMV);
    split_x_kernel<<<TOKENS, 256>>>(x);

    // qkv GEMM -> fused split + head-major scatter
    gemm_ps_kernel<2><<<dim3(N_QKV / 64, TOKENS / 128), 256, GS_SMEM>>>(
        xh, xl, wq_h, wq_l, nullptr, nullptr, TOKENS, N_QKV, DIMV);

    attn_mma_kernel<<<dim3(NBH, NSEQ / 128), 256, ATT_SMEM>>>();

    // proj GEMM + bias
    gemm_ps_kernel<1><<<dim3(DIMV / 64, TOKENS / 128), 256, GS_SMEM>>>(
        ath, atl, wp_h, wp_l, b_proj, out, TOKENS, DIMV, DIMV);
}

// round 13
// speedup vs baseline: 1.0216x; 1.0216x over previous
#include <cuda_runtime.h>
#include <cuda_bf16.h>
#include <cstdint>

#define TOKENS   8192
#define DIMV     1024
#define HEADS    16
#define HD       64
#define NSEQ     1024
#define NBATCH   8
#define ATT_SCALE 0.125f
#define N_QKV    3072
#define NBH      (NBATCH * HEADS)

// ---------------- scratch (__device__ globals; no allocation) ---------------
__device__ __align__(16) __nv_bfloat16 g_xh[(size_t)TOKENS * DIMV];
__device__ __align__(16) __nv_bfloat16 g_xl[(size_t)TOKENS * DIMV];
__device__ __align__(16) __nv_bfloat16 g_atth[(size_t)TOKENS * DIMV];
__device__ __align__(16) __nv_bfloat16 g_attl[(size_t)TOKENS * DIMV];
__device__ __align__(16) __nv_bfloat16 g_wqkv_h[(size_t)N_QKV * DIMV];
__device__ __align__(16) __nv_bfloat16 g_wqkv_l[(size_t)N_QKV * DIMV];
__device__ __align__(16) __nv_bfloat16 g_wproj_h[(size_t)DIMV * DIMV];
__device__ __align__(16) __nv_bfloat16 g_wproj_l[(size_t)DIMV * DIMV];
// head-major split QKV: [bh][n][64]
__device__ __align__(16) __nv_bfloat16 g_qh[(size_t)NBH * NSEQ * HD];
__device__ __align__(16) __nv_bfloat16 g_ql[(size_t)NBH * NSEQ * HD];
__device__ __align__(16) __nv_bfloat16 g_kh[(size_t)NBH * NSEQ * HD];
__device__ __align__(16) __nv_bfloat16 g_kl[(size_t)NBH * NSEQ * HD];
__device__ __align__(16) __nv_bfloat16 g_vh[(size_t)NBH * NSEQ * HD];
__device__ __align__(16) __nv_bfloat16 g_vl[(size_t)NBH * NSEQ * HD];

// ---------------- helpers ----------------
__device__ __forceinline__ uint32_t smem_u32(const void* p) {
    uint32_t a;
    asm("{ .reg .u64 t; cvta.to.shared.u64 t, %1; cvt.u32.u64 %0, t; }" : "=r"(a) : "l"(p));
    return a;
}
__device__ __forceinline__ void ldm4(uint32_t* r, uint32_t addr) {
    asm volatile("ldmatrix.sync.aligned.m8n8.x4.shared.b16 {%0,%1,%2,%3}, [%4];"
                 : "=r"(r[0]), "=r"(r[1]), "=r"(r[2]), "=r"(r[3]) : "r"(addr));
}
__device__ __forceinline__ void ldm4t(uint32_t* r, uint32_t addr) {
    asm volatile("ldmatrix.sync.aligned.m8n8.x4.trans.shared.b16 {%0,%1,%2,%3}, [%4];"
                 : "=r"(r[0]), "=r"(r[1]), "=r"(r[2]), "=r"(r[3]) : "r"(addr));
}
__device__ __forceinline__ void mma_bf16(float* d, const uint32_t* a,
                                         uint32_t b0, uint32_t b1) {
    asm volatile(
        "mma.sync.aligned.m16n8k16.row.col.f32.bf16.bf16.f32 "
        "{%0,%1,%2,%3}, {%4,%5,%6,%7}, {%8,%9}, {%0,%1,%2,%3};"
        : "+f"(d[0]), "+f"(d[1]), "+f"(d[2]), "+f"(d[3])
        : "r"(a[0]), "r"(a[1]), "r"(a[2]), "r"(a[3]), "r"(b0), "r"(b1));
}
__device__ __forceinline__ void bf16_split(float v, __nv_bfloat16& h, __nv_bfloat16& l) {
    h = __float2bfloat16(v);
    l = __float2bfloat16(v - __bfloat162float(h));
}
__device__ __forceinline__ void split_pack(float a, float b, uint32_t& h, uint32_t& l) {
    __nv_bfloat16 ha = __float2bfloat16(a), hb = __float2bfloat16(b);
    float ra = a - __bfloat162float(ha), rb = b - __bfloat162float(hb);
    __nv_bfloat162 H(ha, hb);
    __nv_bfloat162 L(__float2bfloat16(ra), __float2bfloat16(rb));
    h = *reinterpret_cast<uint32_t*>(&H);
    l = *reinterpret_cast<uint32_t*>(&L);
}
#define CP_ASYNC16(s, g) asm volatile("cp.async.cg.shared.global [%0], [%1], 16;" :: "r"(s), "l"(g))
#define CP_COMMIT()      asm volatile("cp.async.commit_group;" ::: "memory")
#define CP_WAIT1()       asm volatile("cp.async.wait_group 1;" ::: "memory")
#define CP_WAIT0()       asm volatile("cp.async.wait_group 0;" ::: "memory")
// XOR-16B swizzled offset within a [rows][8x16B] array
#define SWZ_OFF(row, c)  ((((row) * 8 + ((c) ^ ((row) & 7)))) * 16)

// ---------------------------------------------------------------------------
// Weight transpose + bf16 hi/lo split: W[K,N] -> Th/Tl[N,K]
// ---------------------------------------------------------------------------
__global__ __launch_bounds__(256) void transpose_split_kernel(
    const float* __restrict__ W, __nv_bfloat16* __restrict__ Th,
    __nv_bfloat16* __restrict__ Tl, int K, int N) {
    __shared__ float t[32][33];
    const int tx = threadIdx.x, ty = threadIdx.y;
    const int k0 = blockIdx.x * 32, n0 = blockIdx.y * 32;
    #pragma unroll
    for (int i = 0; i < 4; i++)
        t[ty + i * 8][tx] = W[(size_t)(k0 + ty + i * 8) * N + (n0 + tx)];
    __syncthreads();
    #pragma unroll
    for (int i = 0; i < 4; i++) {
        const float v = t[tx][ty + i * 8];
        __nv_bfloat16 h, l;
        bf16_split(v, h, l);
        const size_t o = (size_t)(n0 + ty + i * 8) * K + (k0 + tx);
        Th[o] = h;
        Tl[o] = l;
    }
}

// ---------------------------------------------------------------------------
// split x fp32 -> xh/xl bf16 (same layout)
// ---------------------------------------------------------------------------
__global__ __launch_bounds__(256) void split_x_kernel(const float* __restrict__ x) {
    const size_t o = (size_t)blockIdx.x * DIMV + threadIdx.x * 4;
    float4 v = *reinterpret_cast<const float4*>(x + o);
    uint32_t h0, l0, h1, l1;
    split_pack(v.x, v.y, h0, l0);
    split_pack(v.z, v.w, h1, l1);
    *reinterpret_cast<uint32_t*>(g_xh + o)     = h0;
    *reinterpret_cast<uint32_t*>(g_xh + o + 2) = h1;
    *reinterpret_cast<uint32_t*>(g_xl + o)     = l0;
    *reinterpret_cast<uint32_t*>(g_xl + o + 2) = l1;
}

// ---------------------------------------------------------------------------
// Pipelined bf16x3 GEMM, pre-split A: C = A @ Bt^T.   (unchanged from R11/R12)
// ---------------------------------------------------------------------------
#define GA_BYTES 16384                     // 128 rows * 128 B
#define GB_BYTES 8192                      // 64 rows * 128 B
#define OFF_AL GA_BYTES
#define OFF_BH (2 * GA_BYTES)
#define OFF_BL (2 * GA_BYTES + GB_BYTES)
#define GS_STAGE (2 * GA_BYTES + 2 * GB_BYTES)   // 49152
#define GS_SMEM  (2 * GS_STAGE)                  // 98304

template<int MODE>
__global__ __launch_bounds__(256, 2) void gemm_ps_kernel(
    const __nv_bfloat16* __restrict__ Ah, const __nv_bfloat16* __restrict__ Al,
    const __nv_bfloat16* __restrict__ Bh, const __nv_bfloat16* __restrict__ Bl,
    const float* __restrict__ bias, float* __restrict__ C,
    int M, int N, int K) {
    extern __shared__ char smem[];
    const uint32_t sb = smem_u32(smem);
    const int tid  = threadIdx.x;
    const int wid  = tid >> 5;
    const int lane = tid & 31;
    const int warp_m = wid >> 1;
    const int warp_n = wid & 1;
    const int row0 = blockIdx.y * 128, col0 = blockIdx.x * 64;
    const int lr = lane & 15, ls = lane >> 4;

    auto load_tile = [&](int kc, int stage) {
        const int k0 = kc * 64;
        const uint32_t sbase = sb + stage * GS_STAGE;
        #pragma unroll
        for (int i = 0; i < 8; i++) {
            const int cid = tid + i * 256;
            const int hl = cid >> 10, rem = cid & 1023, row = rem >> 3, c = rem & 7;
            const __nv_bfloat16* src = hl ? Al : Ah;
            const void* g = src + (size_t)(row0 + row) * K + k0 + c * 8;
            CP_ASYNC16(sbase + hl * OFF_AL + SWZ_OFF(row, c), g);
        }
        #pragma unroll
        for (int i = 0; i < 4; i++) {
            const int x = tid + i * 256;
            const int hl = x >> 9, rem = x & 511, row = rem >> 3, c = rem & 7;
            const __nv_bfloat16* src = hl ? Bl : Bh;
            const void* g = src + (size_t)(col0 + row) * K + k0 + c * 8;
            CP_ASYNC16(sbase + OFF_BH + hl * GB_BYTES + SWZ_OFF(row, c), g);
        }
        CP_COMMIT();
    };

    float acc[2][4][4];
    #pragma unroll
    for (int i = 0; i < 2; i++)
        #pragma unroll
        for (int j = 0; j < 4; j++)
            #pragma unroll
            for (int r = 0; r < 4; r++) acc[i][j][r] = 0.f;

    const int nchunks = K / 64;           // 16
    load_tile(0, 0);

    for (int kc = 0; kc < nchunks; kc++) {
        const int stg = kc & 1;
        if (kc + 1 < nchunks) { load_tile(kc + 1, stg ^ 1); CP_WAIT1(); }
        else                  { CP_WAIT0(); }
        __syncthreads();

        const uint32_t base = sb + stg * GS_STAGE;
        #pragma unroll
        for (int k16 = 0; k16 < 64; k16 += 16) {
            const int cbase = (k16 >> 3) + ls;
            uint32_t b_h[2][4], b_l[2][4];
            #pragma unroll
            for (int p = 0; p < 2; p++) {
                const int r = warp_n * 32 + p * 16 + lr;
                const uint32_t off = SWZ_OFF(r, cbase);
                ldm4(b_h[p], base + OFF_BH + off);
                ldm4(b_l[p], base + OFF_BL + off);
            }
            #pragma unroll
            for (int mi = 0; mi < 2; mi++) {
                uint32_t a_h[4], a_l[4];
                const int r = warp_m * 32 + mi * 16 + lr;
                const uint32_t off = SWZ_OFF(r, cbase);
                ldm4(a_h, base + off);
                ldm4(a_l, base + OFF_AL + off);
                #pragma unroll
                for (int nj = 0; nj < 4; nj++) {
                    const int p = nj >> 1, s = nj & 1;
                    mma_bf16(acc[mi][nj], a_h, b_h[p][s], b_h[p][2 + s]);
                }
                #pragma unroll
                for (int nj = 0; nj < 4; nj++) {
                    const int p = nj >> 1, s = nj & 1;
                    mma_bf16(acc[mi][nj], a_h, b_l[p][s], b_l[p][2 + s]);
                }
                #pragma unroll
                for (int nj = 0; nj < 4; nj++) {
                    const int p = nj >> 1, s = nj & 1;
                    mma_bf16(acc[mi][nj], a_l, b_h[p][s], b_h[p][2 + s]);
                }
            }
        }
        __syncthreads();
    }

    // ---- epilogue ----
    const int er = lane >> 2, ec = (lane & 3) * 2;
    if (MODE == 2) {
        auto scatter = [&](int r, int c, float x, float y) {
            const int qi = c >> 10, dcol = c & 1023;
            const int head = dcol >> 6, dd = dcol & 63;
            const int b = r >> 10, n = r & 1023;
            const size_t off = (((size_t)(b * HEADS + head) * NSEQ) + n) * HD + dd;
            if (qi == 0) { x *= ATT_SCALE; y *= ATT_SCALE; }
            uint32_t h, l;
            split_pack(x, y, h, l);
            __nv_bfloat16* dh = (qi == 0) ? g_qh : (qi == 1) ? g_kh : g_vh;
            __nv_bfloat16* dl = (qi == 0) ? g_ql : (qi == 1) ? g_kl : g_vl;
            *reinterpret_cast<uint32_t*>(dh + off) = h;
            *reinterpret_cast<uint32_t*>(dl + off) = l;
        };
        #pragma unroll
        for (int mi = 0; mi < 2; mi++)
            #pragma unroll
            for (int nj = 0; nj < 4; nj++) {
                const int r = row0 + warp_m * 32 + mi * 16 + er;
                const int c = col0 + warp_n * 32 + nj * 8 + ec;
                scatter(r,     c, acc[mi][nj][0], acc[mi][nj][1]);
                scatter(r + 8, c, acc[mi][nj][2], acc[mi][nj][3]);
            }
    } else {
        #pragma unroll
        for (int mi = 0; mi < 2; mi++)
            #pragma unroll
            for (int nj = 0; nj < 4; nj++) {
                const int r = row0 + warp_m * 32 + mi * 16 + er;
                const int c = col0 + warp_n * 32 + nj * 8 + ec;
                float2 v0 = make_float2(acc[mi][nj][0], acc[mi][nj][1]);
                float2 v1 = make_float2(acc[mi][nj][2], acc[mi][nj][3]);
                if (MODE == 1) {
                    const float b0 = bias[c], b1 = bias[c + 1];
                    v0.x += b0; v0.y += b1;
                    v1.x += b0; v1.y += b1;
                }
                *reinterpret_cast<float2*>(C + (size_t)r * N + c)       = v0;
                *reinterpret_cast<float2*>(C + (size_t)(r + 8) * N + c) = v1;
            }
    }
}

// ---------------------------------------------------------------------------
// Flash attention, mma.sync bf16x3.
// R13: Q fragments reloaded from persistent Q smem each tile (frees ~32 regs)
// + __launch_bounds__(256, 2) -> 2 CTAs/SM.
// ---------------------------------------------------------------------------
#define ATT_SMEM 98304

__global__ __launch_bounds__(256, 2) void attn_mma_kernel() {
    extern __shared__ char smem[];
    const uint32_t sb = smem_u32(smem);
    const int tid = threadIdx.x, wid = tid >> 5, lane = tid & 31;
    const int bh = blockIdx.x;
    const int qt0 = blockIdx.y * 128;
    const size_t hb = (size_t)bh * NSEQ * HD;

    {
        const __nv_bfloat16* qsrc[2] = {g_qh, g_ql};
        #pragma unroll
        for (int i = 0; i < 8; i++) {
            const int cid = tid + i * 256;
            const int arr = cid >> 10, rem = cid & 1023, row = rem >> 3, c = rem & 7;
            const void* g = qsrc[arr] + hb + (size_t)(qt0 + row) * HD + c * 8;
            const uint32_t s = sb + 65536 + arr * 16384 + SWZ_OFF(row, c);
            CP_ASYNC16(s, g);
        }
        CP_COMMIT();
    }
    auto load_kv = [&](int kt, int stage) {
        const __nv_bfloat16* src[4] = {g_kh, g_kl, g_vh, g_vl};
        const int key0 = kt * 64;
        #pragma unroll
        for (int i = 0; i < 8; i++) {
            const int cid = tid + i * 256;
            const int arr = cid >> 9, rem = cid & 511, key = rem >> 3, c = rem & 7;
            const void* g = src[arr] + hb + (size_t)(key0 + key) * HD + c * 8;
            const uint32_t s = sb + stage * 32768 + arr * 8192 + SWZ_OFF(key, c);
            CP_ASYNC16(s, g);
        }
        CP_COMMIT();
    };
    load_kv(0, 0);

    CP_WAIT1();
    __syncthreads();

    const int qrow = wid * 16 + (lane & 15);   // Q fragment row for this lane

    float o[8][4];
    #pragma unroll
    for (int i = 0; i < 8; i++)
        #pragma unroll
        for (int j = 0; j < 4; j++) o[i][j] = 0.f;
    float m0 = -1e30f, m1 = -1e30f, l0 = 0.f, l1 = 0.f;

    for (int kt = 0; kt < 16; kt++) {
        const int stg = kt & 1;
        if (kt + 1 < 16) { load_kv(kt + 1, stg ^ 1); CP_WAIT1(); }
        else             { CP_WAIT0(); }
        __syncthreads();

        float sc[8][4];
        #pragma unroll
        for (int i = 0; i < 8; i++)
            #pragma unroll
            for (int j = 0; j < 4; j++) sc[i][j] = 0.f;
        const uint32_t kbh = sb + stg * 32768, kbl = kbh + 8192;
        #pragma unroll
        for (int ks = 0; ks < 4; ks++) {
            // reload Q fragments from persistent Q smem (region untouched by KV)
            uint32_t qh4[4], ql4[4];
            {
                const int c = ks * 2 + (lane >> 4);
                const uint32_t qoff = SWZ_OFF(qrow, c);
                ldm4(qh4, sb + 65536 + qoff);
                ldm4(ql4, sb + 65536 + 16384 + qoff);
            }
            #pragma unroll
            for (int g = 0; g < 4; g++) {
                const int key = g * 16 + (lane & 15);
                const int c   = ks * 2 + (lane >> 4);
                const uint32_t off = SWZ_OFF(key, c);
                uint32_t kh4[4], kl4[4];
                ldm4(kh4, kbh + off);
                ldm4(kl4, kbl + off);
                float* d0 = sc[2 * g];
                float* d1 = sc[2 * g + 1];
                mma_bf16(d0, qh4, kh4[0], kh4[2]);
                mma_bf16(d1, qh4, kh4[1], kh4[3]);
                mma_bf16(d0, qh4, kl4[0], kl4[2]);
                mma_bf16(d1, qh4, kl4[1], kl4[3]);
                mma_bf16(d0, ql4, kh4[0], kh4[2]);
                mma_bf16(d1, ql4, kh4[1], kh4[3]);
            }
        }

        float mx0 = sc[0][0], mx1 = sc[0][2];
        #pragma unroll
        for (int nt = 0; nt < 8; nt++) {
            mx0 = fmaxf(mx0, fmaxf(sc[nt][0], sc[nt][1]));
            mx1 = fmaxf(mx1, fmaxf(sc[nt][2], sc[nt][3]));
        }
        mx0 = fmaxf(mx0, __shfl_xor_sync(0xffffffffu, mx0, 1));
        mx0 = fmaxf(mx0, __shfl_xor_sync(0xffffffffu, mx0, 2));
        mx1 = fmaxf(mx1, __shfl_xor_sync(0xffffffffu, mx1, 1));
        mx1 = fmaxf(mx1, __shfl_xor_sync(0xffffffffu, mx1, 2));
        const float mn0 = fmaxf(m0, mx0), mn1 = fmaxf(m1, mx1);
        const float c0 = __expf(m0 - mn0), c1 = __expf(m1 - mn1);
        float s0 = 0.f, s1 = 0.f;
        #pragma unroll
        for (int nt = 0; nt < 8; nt++) {
            float p0 = __expf(sc[nt][0] - mn0); sc[nt][0] = p0; s0 += p0;
            float p1 = __expf(sc[nt][1] - mn0); sc[nt][1] = p1; s0 += p1;
            float p2 = __expf(sc[nt][2] - mn1); sc[nt][2] = p2; s1 += p2;
            float p3 = __expf(sc[nt][3] - mn1); sc[nt][3] = p3; s1 += p3;
        }
        s0 += __shfl_xor_sync(0xffffffffu, s0, 1);
        s0 += __shfl_xor_sync(0xffffffffu, s0, 2);
        s1 += __shfl_xor_sync(0xffffffffu, s1, 1);
        s1 += __shfl_xor_sync(0xffffffffu, s1, 2);
        l0 = l0 * c0 + s0; l1 = l1 * c1 + s1;
        m0 = mn0; m1 = mn1;
        #pragma unroll
        for (int dt = 0; dt < 8; dt++) {
            o[dt][0] *= c0; o[dt][1] *= c0;
            o[dt][2] *= c1; o[dt][3] *= c1;
        }

        const uint32_t vbh = sb + stg * 32768 + 16384, vbl = vbh + 8192;
        #pragma unroll
        for (int kk = 0; kk < 4; kk++) {
            uint32_t pah[4], pal[4];
            split_pack(sc[2 * kk][0],     sc[2 * kk][1],     pah[0], pal[0]);
            split_pack(sc[2 * kk][2],     sc[2 * kk][3],     pah[1], pal[1]);
            split_pack(sc[2 * kk + 1][0], sc[2 * kk + 1][1], pah[2], pal[2]);
            split_pack(sc[2 * kk + 1][2], sc[2 * kk + 1][3], pah[3], pal[3]);
            #pragma unroll
            for (int dg = 0; dg < 4; dg++) {
                const int key = kk * 16 + (lane & 15);
                const int c   = dg * 2 + (lane >> 4);
                const uint32_t off = SWZ_OFF(key, c);
                uint32_t vh4[4], vl4[4];
                ldm4t(vh4, vbh + off);
                ldm4t(vl4, vbl + off);
                float* d0 = o[2 * dg];
                float* d1 = o[2 * dg + 1];
                mma_bf16(d0, pah, vh4[0], vh4[1]);
                mma_bf16(d1, pah, vh4[2], vh4[3]);
                mma_bf16(d0, pah, vl4[0], vl4[1]);
                mma_bf16(d1, pah, vl4[2], vl4[3]);
                mma_bf16(d0, pal, vh4[0], vh4[1]);
                mma_bf16(d1, pal, vh4[2], vh4[3]);
            }
        }
        __syncthreads();
    }

    // ---- epilogue: write split bf16 attention output (token-major [8192,1024]) ----
    const float i0 = 1.f / l0, i1 = 1.f / l1;
    const int b = bh >> 4, h = bh & 15;
    const int r0 = qt0 + wid * 16 + (lane >> 2);
    const size_t base = (size_t)(b * NSEQ + r0) * DIMV + h * HD + (lane & 3) * 2;
    #pragma unroll
    for (int dt = 0; dt < 8; dt++) {
        uint32_t h0, l0v, h1, l1v;
        split_pack(o[dt][0] * i0, o[dt][1] * i0, h0, l0v);
        split_pack(o[dt][2] * i1, o[dt][3] * i1, h1, l1v);
        *reinterpret_cast<uint32_t*>(g_atth + base + dt * 8)            = h0;
        *reinterpret_cast<uint32_t*>(g_attl + base + dt * 8)            = l0v;
        *reinterpret_cast<uint32_t*>(g_atth + base + 8 * DIMV + dt * 8) = h1;
        *reinterpret_cast<uint32_t*>(g_attl + base + 8 * DIMV + dt * 8) = l1v;
    }
}

// ---------------------------------------------------------------------------
extern "C" void kernel_launch(void* const* d_in, const int* in_sizes, int n_in,
                              void* d_out, int out_size) {
    const float* x      = (const float*)d_in[0];
    const float* w_qkv  = (const float*)d_in[1];
    const float* w_proj = (const float*)d_in[2];
    const float* b_proj = (const float*)d_in[3];
    float* out = (float*)d_out;

    __nv_bfloat16 *wq_h, *wq_l, *wp_h, *wp_l, *xh, *xl, *ath, *atl;
    cudaGetSymbolAddress((void**)&wq_h, g_wqkv_h);
    cudaGetSymbolAddress((void**)&wq_l, g_wqkv_l);
    cudaGetSymbolAddress((void**)&wp_h, g_wproj_h);
    cudaGetSymbolAddress((void**)&wp_l, g_wproj_l);
    cudaGetSymbolAddress((void**)&xh, g_xh);
    cudaGetSymbolAddress((void**)&xl, g_xl);
    cudaGetSymbolAddress((void**)&ath, g_atth);
    cudaGetSymbolAddress((void**)&atl, g_attl);

    cudaFuncSetAttribute(attn_mma_kernel,
                         cudaFuncAttributeMaxDynamicSharedMemorySize, ATT_SMEM);
    cudaFuncSetAttribute(gemm_ps_kernel<1>,
                         cudaFuncAttributeMaxDynamicSharedMemorySize, GS_SMEM);
    cudaFuncSetAttribute(gemm_ps_kernel<2>,
                         cudaFuncAttributeMaxDynamicSharedMemorySize, GS_SMEM);

    transpose_split_kernel<<<dim3(DIMV / 32, N_QKV / 32), dim3(32, 8)>>>(
        w_qkv, wq_h, wq_l, DIMV, N_QKV);
    transpose_split_kernel<<<dim3(DIMV / 32, DIMV / 32), dim3(32, 8)>>>(
        w_proj, wp_h, wp_l, DIMV, DIMV);
    split_x_kernel<<<TOKENS, 256>>>(x);

    // qkv GEMM -> fused split + head-major scatter
    gemm_ps_kernel<2><<<dim3(N_QKV / 64, TOKENS / 128), 256, GS_SMEM>>>(
        xh, xl, wq_h, wq_l, nullptr, nullptr, TOKENS, N_QKV, DIMV);

    attn_mma_kernel<<<dim3(NBH, NSEQ / 128), 256, ATT_SMEM>>>();

    // proj GEMM + bias
    gemm_ps_kernel<1><<<dim3(DIMV / 64, TOKENS / 128), 256, GS_SMEM>>>(
        ath, atl, wp_h, wp_l, b_proj, out, TOKENS, DIMV, DIMV);
}

// round 14
// speedup vs baseline: 1.0224x; 1.0008x over previous
#include <cuda_runtime.h>
#include <cuda_bf16.h>
#include <cstdint>

#define TOKENS   8192
#define DIMV     1024
#define HEADS    16
#define HD       64
#define NSEQ     1024
#define NBATCH   8
#define ATT_SCALE 0.125f
#define N_QKV    3072
#define NBH      (NBATCH * HEADS)

// ---------------- scratch (__device__ globals; no allocation) ---------------
__device__ __align__(16) __nv_bfloat16 g_xh[(size_t)TOKENS * DIMV];
__device__ __align__(16) __nv_bfloat16 g_xl[(size_t)TOKENS * DIMV];
__device__ __align__(16) __nv_bfloat16 g_atth[(size_t)TOKENS * DIMV];
__device__ __align__(16) __nv_bfloat16 g_attl[(size_t)TOKENS * DIMV];
__device__ __align__(16) __nv_bfloat16 g_wqkv_h[(size_t)N_QKV * DIMV];
__device__ __align__(16) __nv_bfloat16 g_wqkv_l[(size_t)N_QKV * DIMV];
__device__ __align__(16) __nv_bfloat16 g_wproj_h[(size_t)DIMV * DIMV];
__device__ __align__(16) __nv_bfloat16 g_wproj_l[(size_t)DIMV * DIMV];
// head-major split QKV: [bh][n][64]
__device__ __align__(16) __nv_bfloat16 g_qh[(size_t)NBH * NSEQ * HD];
__device__ __align__(16) __nv_bfloat16 g_ql[(size_t)NBH * NSEQ * HD];
__device__ __align__(16) __nv_bfloat16 g_kh[(size_t)NBH * NSEQ * HD];
__device__ __align__(16) __nv_bfloat16 g_kl[(size_t)NBH * NSEQ * HD];
__device__ __align__(16) __nv_bfloat16 g_vh[(size_t)NBH * NSEQ * HD];
__device__ __align__(16) __nv_bfloat16 g_vl[(size_t)NBH * NSEQ * HD];

// ---------------- helpers ----------------
__device__ __forceinline__ uint32_t smem_u32(const void* p) {
    uint32_t a;
    asm("{ .reg .u64 t; cvta.to.shared.u64 t, %1; cvt.u32.u64 %0, t; }" : "=r"(a) : "l"(p));
    return a;
}
__device__ __forceinline__ void ldm4(uint32_t* r, uint32_t addr) {
    asm volatile("ldmatrix.sync.aligned.m8n8.x4.shared.b16 {%0,%1,%2,%3}, [%4];"
                 : "=r"(r[0]), "=r"(r[1]), "=r"(r[2]), "=r"(r[3]) : "r"(addr));
}
__device__ __forceinline__ void ldm4t(uint32_t* r, uint32_t addr) {
    asm volatile("ldmatrix.sync.aligned.m8n8.x4.trans.shared.b16 {%0,%1,%2,%3}, [%4];"
                 : "=r"(r[0]), "=r"(r[1]), "=r"(r[2]), "=r"(r[3]) : "r"(addr));
}
__device__ __forceinline__ void mma_bf16(float* d, const uint32_t* a,
                                         uint32_t b0, uint32_t b1) {
    asm volatile(
        "mma.sync.aligned.m16n8k16.row.col.f32.bf16.bf16.f32 "
        "{%0,%1,%2,%3}, {%4,%5,%6,%7}, {%8,%9}, {%0,%1,%2,%3};"
        : "+f"(d[0]), "+f"(d[1]), "+f"(d[2]), "+f"(d[3])
        : "r"(a[0]), "r"(a[1]), "r"(a[2]), "r"(a[3]), "r"(b0), "r"(b1));
}
__device__ __forceinline__ void bf16_split(float v, __nv_bfloat16& h, __nv_bfloat16& l) {
    h = __float2bfloat16(v);
    l = __float2bfloat16(v - __bfloat162float(h));
}
__device__ __forceinline__ void split_pack(float a, float b, uint32_t& h, uint32_t& l) {
    __nv_bfloat16 ha = __float2bfloat16(a), hb = __float2bfloat16(b);
    float ra = a - __bfloat162float(ha), rb = b - __bfloat162float(hb);
    __nv_bfloat162 H(ha, hb);
    __nv_bfloat162 L(__float2bfloat16(ra), __float2bfloat16(rb));
    h = *reinterpret_cast<uint32_t*>(&H);
    l = *reinterpret_cast<uint32_t*>(&L);
}
#define CP_ASYNC16(s, g) asm volatile("cp.async.cg.shared.global [%0], [%1], 16;" :: "r"(s), "l"(g))
#define CP_COMMIT()      asm volatile("cp.async.commit_group;" ::: "memory")
#define CP_WAIT1()       asm volatile("cp.async.wait_group 1;" ::: "memory")
#define CP_WAIT0()       asm volatile("cp.async.wait_group 0;" ::: "memory")
// XOR-16B swizzled offset within a [rows][8x16B] array
#define SWZ_OFF(row, c)  ((((row) * 8 + ((c) ^ ((row) & 7)))) * 16)

// ---------------------------------------------------------------------------
// Weight transpose + bf16 hi/lo split: W[K,N] -> Th/Tl[N,K]
// ---------------------------------------------------------------------------
__global__ __launch_bounds__(256) void transpose_split_kernel(
    const float* __restrict__ W, __nv_bfloat16* __restrict__ Th,
    __nv_bfloat16* __restrict__ Tl, int K, int N) {
    __shared__ float t[32][33];
    const int tx = threadIdx.x, ty = threadIdx.y;
    const int k0 = blockIdx.x * 32, n0 = blockIdx.y * 32;
    #pragma unroll
    for (int i = 0; i < 4; i++)
        t[ty + i * 8][tx] = W[(size_t)(k0 + ty + i * 8) * N + (n0 + tx)];
    __syncthreads();
    #pragma unroll
    for (int i = 0; i < 4; i++) {
        const float v = t[tx][ty + i * 8];
        __nv_bfloat16 h, l;
        bf16_split(v, h, l);
        const size_t o = (size_t)(n0 + ty + i * 8) * K + (k0 + tx);
        Th[o] = h;
        Tl[o] = l;
    }
}

// ---------------------------------------------------------------------------
// split x fp32 -> xh/xl bf16 (same layout)
// ---------------------------------------------------------------------------
__global__ __launch_bounds__(256) void split_x_kernel(const float* __restrict__ x) {
    const size_t o = (size_t)blockIdx.x * DIMV + threadIdx.x * 4;
    float4 v = *reinterpret_cast<const float4*>(x + o);
    uint32_t h0, l0, h1, l1;
    split_pack(v.x, v.y, h0, l0);
    split_pack(v.z, v.w, h1, l1);
    *reinterpret_cast<uint32_t*>(g_xh + o)     = h0;
    *reinterpret_cast<uint32_t*>(g_xh + o + 2) = h1;
    *reinterpret_cast<uint32_t*>(g_xl + o)     = l0;
    *reinterpret_cast<uint32_t*>(g_xl + o + 2) = l1;
}

// ---------------------------------------------------------------------------
// Pipelined bf16x3 GEMM, pre-split A: C = A @ Bt^T.
// R14: per-warp k16 phase stagger -- warps (wid>>2)&1==1 process k16 steps in
// rotated order so co-resident SMSP warps anti-phase LDSM vs MMA blocks.
// ---------------------------------------------------------------------------
#define GA_BYTES 16384                     // 128 rows * 128 B
#define GB_BYTES 8192                      // 64 rows * 128 B
#define OFF_AL GA_BYTES
#define OFF_BH (2 * GA_BYTES)
#define OFF_BL (2 * GA_BYTES + GB_BYTES)
#define GS_STAGE (2 * GA_BYTES + 2 * GB_BYTES)   // 49152
#define GS_SMEM  (2 * GS_STAGE)                  // 98304

template<int MODE>
__global__ __launch_bounds__(256, 2) void gemm_ps_kernel(
    const __nv_bfloat16* __restrict__ Ah, const __nv_bfloat16* __restrict__ Al,
    const __nv_bfloat16* __restrict__ Bh, const __nv_bfloat16* __restrict__ Bl,
    const float* __restrict__ bias, float* __restrict__ C,
    int M, int N, int K) {
    extern __shared__ char smem[];
    const uint32_t sb = smem_u32(smem);
    const int tid  = threadIdx.x;
    const int wid  = tid >> 5;
    const int lane = tid & 31;
    const int warp_m = wid >> 1;
    const int warp_n = wid & 1;
    const int row0 = blockIdx.y * 128, col0 = blockIdx.x * 64;
    const int lr = lane & 15, ls = lane >> 4;
    const int kph = ((wid >> 2) & 1) * 2;   // anti-phase between SMSP co-residents

    auto load_tile = [&](int kc, int stage) {
        const int k0 = kc * 64;
        const uint32_t sbase = sb + stage * GS_STAGE;
        #pragma unroll
        for (int i = 0; i < 8; i++) {
            const int cid = tid + i * 256;
            const int hl = cid >> 10, rem = cid & 1023, row = rem >> 3, c = rem & 7;
            const __nv_bfloat16* src = hl ? Al : Ah;
            const void* g = src + (size_t)(row0 + row) * K + k0 + c * 8;
            CP_ASYNC16(sbase + hl * OFF_AL + SWZ_OFF(row, c), g);
        }
        #pragma unroll
        for (int i = 0; i < 4; i++) {
            const int x = tid + i * 256;
            const int hl = x >> 9, rem = x & 511, row = rem >> 3, c = rem & 7;
            const __nv_bfloat16* src = hl ? Bl : Bh;
            const void* g = src + (size_t)(col0 + row) * K + k0 + c * 8;
            CP_ASYNC16(sbase + OFF_BH + hl * GB_BYTES + SWZ_OFF(row, c), g);
        }
        CP_COMMIT();
    };

    float acc[2][4][4];
    #pragma unroll
    for (int i = 0; i < 2; i++)
        #pragma unroll
        for (int j = 0; j < 4; j++)
            #pragma unroll
            for (int r = 0; r < 4; r++) acc[i][j][r] = 0.f;

    const int nchunks = K / 64;           // 16
    load_tile(0, 0);

    for (int kc = 0; kc < nchunks; kc++) {
        const int stg = kc & 1;
        if (kc + 1 < nchunks) { load_tile(kc + 1, stg ^ 1); CP_WAIT1(); }
        else                  { CP_WAIT0(); }
        __syncthreads();

        const uint32_t base = sb + stg * GS_STAGE;
        #pragma unroll
        for (int t = 0; t < 4; t++) {
            const int kstep = (t + kph) & 3;       // rotated k16 order per phase
            const int cbase = kstep * 2 + ls;
            uint32_t b_h[2][4], b_l[2][4];
            #pragma unroll
            for (int p = 0; p < 2; p++) {
                const int r = warp_n * 32 + p * 16 + lr;
                const uint32_t off = SWZ_OFF(r, cbase);
                ldm4(b_h[p], base + OFF_BH + off);
                ldm4(b_l[p], base + OFF_BL + off);
            }
            #pragma unroll
            for (int mi = 0; mi < 2; mi++) {
                uint32_t a_h[4], a_l[4];
                const int r = warp_m * 32 + mi * 16 + lr;
                const uint32_t off = SWZ_OFF(r, cbase);
                ldm4(a_h, base + off);
                ldm4(a_l, base + OFF_AL + off);
                #pragma unroll
                for (int nj = 0; nj < 4; nj++) {
                    const int p = nj >> 1, s = nj & 1;
                    mma_bf16(acc[mi][nj], a_h, b_h[p][s], b_h[p][2 + s]);
                }
                #pragma unroll
                for (int nj = 0; nj < 4; nj++) {
                    const int p = nj >> 1, s = nj & 1;
                    mma_bf16(acc[mi][nj], a_h, b_l[p][s], b_l[p][2 + s]);
                }
                #pragma unroll
                for (int nj = 0; nj < 4; nj++) {
                    const int p = nj >> 1, s = nj & 1;
                    mma_bf16(acc[mi][nj], a_l, b_h[p][s], b_h[p][2 + s]);
                }
            }
        }
        __syncthreads();
    }

    // ---- epilogue ----
    const int er = lane >> 2, ec = (lane & 3) * 2;
    if (MODE == 2) {
        auto scatter = [&](int r, int c, float x, float y) {
            const int qi = c >> 10, dcol = c & 1023;
            const int head = dcol >> 6, dd = dcol & 63;
            const int b = r >> 10, n = r & 1023;
            const size_t off = (((size_t)(b * HEADS + head) * NSEQ) + n) * HD + dd;
            if (qi == 0) { x *= ATT_SCALE; y *= ATT_SCALE; }
            uint32_t h, l;
            split_pack(x, y, h, l);
            __nv_bfloat16* dh = (qi == 0) ? g_qh : (qi == 1) ? g_kh : g_vh;
            __nv_bfloat16* dl = (qi == 0) ? g_ql : (qi == 1) ? g_kl : g_vl;
            *reinterpret_cast<uint32_t*>(dh + off) = h;
            *reinterpret_cast<uint32_t*>(dl + off) = l;
        };
        #pragma unroll
        for (int mi = 0; mi < 2; mi++)
            #pragma unroll
            for (int nj = 0; nj < 4; nj++) {
                const int r = row0 + warp_m * 32 + mi * 16 + er;
                const int c = col0 + warp_n * 32 + nj * 8 + ec;
                scatter(r,     c, acc[mi][nj][0], acc[mi][nj][1]);
                scatter(r + 8, c, acc[mi][nj][2], acc[mi][nj][3]);
            }
    } else {
        #pragma unroll
        for (int mi = 0; mi < 2; mi++)
            #pragma unroll
            for (int nj = 0; nj < 4; nj++) {
                const int r = row0 + warp_m * 32 + mi * 16 + er;
                const int c = col0 + warp_n * 32 + nj * 8 + ec;
                float2 v0 = make_float2(acc[mi][nj][0], acc[mi][nj][1]);
                float2 v1 = make_float2(acc[mi][nj][2], acc[mi][nj][3]);
                if (MODE == 1) {
                    const float b0 = bias[c], b1 = bias[c + 1];
                    v0.x += b0; v0.y += b1;
                    v1.x += b0; v1.y += b1;
                }
                *reinterpret_cast<float2*>(C + (size_t)r * N + c)       = v0;
                *reinterpret_cast<float2*>(C + (size_t)(r + 8) * N + c) = v1;
            }
    }
}

// ---------------------------------------------------------------------------
// Flash attention, mma.sync bf16x3. (unchanged from R13)
// ---------------------------------------------------------------------------
#define ATT_SMEM 98304

__global__ __launch_bounds__(256, 2) void attn_mma_kernel() {
    extern __shared__ char smem[];
    const uint32_t sb = smem_u32(smem);
    const int tid = threadIdx.x, wid = tid >> 5, lane = tid & 31;
    const int bh = blockIdx.x;
    const int qt0 = blockIdx.y * 128;
    const size_t hb = (size_t)bh * NSEQ * HD;

    {
        const __nv_bfloat16* qsrc[2] = {g_qh, g_ql};
        #pragma unroll
        for (int i = 0; i < 8; i++) {
            const int cid = tid + i * 256;
            const int arr = cid >> 10, rem = cid & 1023, row = rem >> 3, c = rem & 7;
            const void* g = qsrc[arr] + hb + (size_t)(qt0 + row) * HD + c * 8;
            const uint32_t s = sb + 65536 + arr * 16384 + SWZ_OFF(row, c);
            CP_ASYNC16(s, g);
        }
        CP_COMMIT();
    }
    auto load_kv = [&](int kt, int stage) {
        const __nv_bfloat16* src[4] = {g_kh, g_kl, g_vh, g_vl};
        const int key0 = kt * 64;
        #pragma unroll
        for (int i = 0; i < 8; i++) {
            const int cid = tid + i * 256;
            const int arr = cid >> 9, rem = cid & 511, key = rem >> 3, c = rem & 7;
            const void* g = src[arr] + hb + (size_t)(key0 + key) * HD + c * 8;
            const uint32_t s = sb + stage * 32768 + arr * 8192 + SWZ_OFF(key, c);
            CP_ASYNC16(s, g);
        }
        CP_COMMIT();
    };
    load_kv(0, 0);

    CP_WAIT1();
    __syncthreads();

    const int qrow = wid * 16 + (lane & 15);

    float o[8][4];
    #pragma unroll
    for (int i = 0; i < 8; i++)
        #pragma unroll
        for (int j = 0; j < 4; j++) o[i][j] = 0.f;
    float m0 = -1e30f, m1 = -1e30f, l0 = 0.f, l1 = 0.f;

    for (int kt = 0; kt < 16; kt++) {
        const int stg = kt & 1;
        if (kt + 1 < 16) { load_kv(kt + 1, stg ^ 1); CP_WAIT1(); }
        else             { CP_WAIT0(); }
        __syncthreads();

        float sc[8][4];
        #pragma unroll
        for (int i = 0; i < 8; i++)
            #pragma unroll
            for (int j = 0; j < 4; j++) sc[i][j] = 0.f;
        const uint32_t kbh = sb + stg * 32768, kbl = kbh + 8192;
        #pragma unroll
        for (int ks = 0; ks < 4; ks++) {
            uint32_t qh4[4], ql4[4];
            {
                const int c = ks * 2 + (lane >> 4);
                const uint32_t qoff = SWZ_OFF(qrow, c);
                ldm4(qh4, sb + 65536 + qoff);
                ldm4(ql4, sb + 65536 + 16384 + qoff);
            }
            #pragma unroll
            for (int g = 0; g < 4; g++) {
                const int key = g * 16 + (lane & 15);
                const int c   = ks * 2 + (lane >> 4);
                const uint32_t off = SWZ_OFF(key, c);
                uint32_t kh4[4], kl4[4];
                ldm4(kh4, kbh + off);
                ldm4(kl4, kbl + off);
                float* d0 = sc[2 * g];
                float* d1 = sc[2 * g + 1];
                mma_bf16(d0, qh4, kh4[0], kh4[2]);
                mma_bf16(d1, qh4, kh4[1], kh4[3]);
                mma_bf16(d0, qh4, kl4[0], kl4[2]);
                mma_bf16(d1, qh4, kl4[1], kl4[3]);
                mma_bf16(d0, ql4, kh4[0], kh4[2]);
                mma_bf16(d1, ql4, kh4[1], kh4[3]);
            }
        }

        float mx0 = sc[0][0], mx1 = sc[0][2];
        #pragma unroll
        for (int nt = 0; nt < 8; nt++) {
            mx0 = fmaxf(mx0, fmaxf(sc[nt][0], sc[nt][1]));
            mx1 = fmaxf(mx1, fmaxf(sc[nt][2], sc[nt][3]));
        }
        mx0 = fmaxf(mx0, __shfl_xor_sync(0xffffffffu, mx0, 1));
        mx0 = fmaxf(mx0, __shfl_xor_sync(0xffffffffu, mx0, 2));
        mx1 = fmaxf(mx1, __shfl_xor_sync(0xffffffffu, mx1, 1));
        mx1 = fmaxf(mx1, __shfl_xor_sync(0xffffffffu, mx1, 2));
        const float mn0 = fmaxf(m0, mx0), mn1 = fmaxf(m1, mx1);
        const float c0 = __expf(m0 - mn0), c1 = __expf(m1 - mn1);
        float s0 = 0.f, s1 = 0.f;
        #pragma unroll
        for (int nt = 0; nt < 8; nt++) {
            float p0 = __expf(sc[nt][0] - mn0); sc[nt][0] = p0; s0 += p0;
            float p1 = __expf(sc[nt][1] - mn0); sc[nt][1] = p1; s0 += p1;
            float p2 = __expf(sc[nt][2] - mn1); sc[nt][2] = p2; s1 += p2;
            float p3 = __expf(sc[nt][3] - mn1); sc[nt][3] = p3; s1 += p3;
        }
        s0 += __shfl_xor_sync(0xffffffffu, s0, 1);
        s0 += __shfl_xor_sync(0xffffffffu, s0, 2);
        s1 += __shfl_xor_sync(0xffffffffu, s1, 1);
        s1 += __shfl_xor_sync(0xffffffffu, s1, 2);
        l0 = l0 * c0 + s0; l1 = l1 * c1 + s1;
        m0 = mn0; m1 = mn1;
        #pragma unroll
        for (int dt = 0; dt < 8; dt++) {
            o[dt][0] *= c0; o[dt][1] *= c0;
            o[dt][2] *= c1; o[dt][3] *= c1;
        }

        const uint32_t vbh = sb + stg * 32768 + 16384, vbl = vbh + 8192;
        #pragma unroll
        for (int kk = 0; kk < 4; kk++) {
            uint32_t pah[4], pal[4];
            split_pack(sc[2 * kk][0],     sc[2 * kk][1],     pah[0], pal[0]);
            split_pack(sc[2 * kk][2],     sc[2 * kk][3],     pah[1], pal[1]);
            split_pack(sc[2 * kk + 1][0], sc[2 * kk + 1][1], pah[2], pal[2]);
            split_pack(sc[2 * kk + 1][2], sc[2 * kk + 1][3], pah[3], pal[3]);
            #pragma unroll
            for (int dg = 0; dg < 4; dg++) {
                const int key = kk * 16 + (lane & 15);
                const int c   = dg * 2 + (lane >> 4);
                const uint32_t off = SWZ_OFF(key, c);
                uint32_t vh4[4], vl4[4];
                ldm4t(vh4, vbh + off);
                ldm4t(vl4, vbl + off);
                float* d0 = o[2 * dg];
                float* d1 = o[2 * dg + 1];
                mma_bf16(d0, pah, vh4[0], vh4[1]);
                mma_bf16(d1, pah, vh4[2], vh4[3]);
                mma_bf16(d0, pah, vl4[0], vl4[1]);
                mma_bf16(d1, pah, vl4[2], vl4[3]);
                mma_bf16(d0, pal, vh4[0], vh4[1]);
                mma_bf16(d1, pal, vh4[2], vh4[3]);
            }
        }
        __syncthreads();
    }

    // ---- epilogue: write split bf16 attention output (token-major [8192,1024]) ----
    const float i0 = 1.f / l0, i1 = 1.f / l1;
    const int b = bh >> 4, h = bh & 15;
    const int r0 = qt0 + wid * 16 + (lane >> 2);
    const size_t base = (size_t)(b * NSEQ + r0) * DIMV + h * HD + (lane & 3) * 2;
    #pragma unroll
    for (int dt = 0; dt < 8; dt++) {
        uint32_t h0, l0v, h1, l1v;
        split_pack(o[dt][0] * i0, o[dt][1] * i0, h0, l0v);
        split_pack(o[dt][2] * i1, o[dt][3] * i1, h1, l1v);
        *reinterpret_cast<uint32_t*>(g_atth + base + dt * 8)            = h0;
        *reinterpret_cast<uint32_t*>(g_attl + base + dt * 8)            = l0v;
        *reinterpret_cast<uint32_t*>(g_atth + base + 8 * DIMV + dt * 8) = h1;
        *reinterpret_cast<uint32_t*>(g_attl + base + 8 * DIMV + dt * 8) = l1v;
    }
}

// ---------------------------------------------------------------------------
extern "C" void kernel_launch(void* const* d_in, const int* in_sizes, int n_in,
                              void* d_out, int out_size) {
    const float* x      = (const float*)d_in[0];
    const float* w_qkv  = (const float*)d_in[1];
    const float* w_proj = (const float*)d_in[2];
    const float* b_proj = (const float*)d_in[3];
    float* out = (float*)d_out;

    __nv_bfloat16 *wq_h, *wq_l, *wp_h, *wp_l, *xh, *xl, *ath, *atl;
    cudaGetSymbolAddress((void**)&wq_h, g_wqkv_h);
    cudaGetSymbolAddress((void**)&wq_l, g_wqkv_l);
    cudaGetSymbolAddress((void**)&wp_h, g_wproj_h);
    cudaGetSymbolAddress((void**)&wp_l, g_wproj_l);
    cudaGetSymbolAddress((void**)&xh, g_xh);
    cudaGetSymbolAddress((void**)&xl, g_xl);
    cudaGetSymbolAddress((void**)&ath, g_atth);
    cudaGetSymbolAddress((void**)&atl, g_attl);

    cudaFuncSetAttribute(attn_mma_kernel,
                         cudaFuncAttributeMaxDynamicSharedMemorySize, ATT_SMEM);
    cudaFuncSetAttribute(gemm_ps_kernel<1>,
                         cudaFuncAttributeMaxDynamicSharedMemorySize, GS_SMEM);
    cudaFuncSetAttribute(gemm_ps_kernel<2>,
                         cudaFuncAttributeMaxDynamicSharedMemorySize, GS_SMEM);

    transpose_split_kernel<<<dim3(DIMV / 32, N_QKV / 32), dim3(32, 8)>>>(
        w_qkv, wq_h, wq_l, DIMV, N_QKV);
    transpose_split_kernel<<<dim3(DIMV / 32, DIMV / 32), dim3(32, 8)>>>(
        w_proj, wp_h, wp_l, DIMV, DIMV);
    split_x_kernel<<<TOKENS, 256>>>(x);

    // qkv GEMM -> fused split + head-major scatter
    gemm_ps_kernel<2><<<dim3(N_QKV / 64, TOKENS / 128), 256, GS_SMEM>>>(
        xh, xl, wq_h, wq_l, nullptr, nullptr, TOKENS, N_QKV, DIMV);

    attn_mma_kernel<<<dim3(NBH, NSEQ / 128), 256, ATT_SMEM>>>();

    // proj GEMM + bias
    gemm_ps_kernel<1><<<dim3(DIMV / 64, TOKENS / 128), 256, GS_SMEM>>>(
        ath, atl, wp_h, wp_l, b_proj, out, TOKENS, DIMV, DIMV);
}